// round 14
// baseline (speedup 1.0000x reference)
#include <cuda_runtime.h>
#include <cuda_fp16.h>
#include <cstdint>
#include <cstring>
#include <math.h>

#define NSEG   4096
#define NVOT   1048576
#define NCAND  32
#define EMB    128
#define TILE_M 128
#define NTILES (NVOT / TILE_M)   // 8192

// 256B-pitch shared-tile swizzle: XOR 16B-unit index with row low bits
#define SWB(o) ((o) ^ (((o) >> 4) & 0x70))

// ------------------------------------------------------------------
// Device scratch (allocation-free rule: __device__ globals)
// ------------------------------------------------------------------
__device__ float g_agg[NSEG * EMB];
__device__ __half g_w1[128 * 64];
__device__ __half g_w2[128 * 128];
__device__ __half g_w3[128 * 128];

// ------------------------------------------------------------------
// PTX helpers (sm_80-era: legal in compute_103 PTX)
// ------------------------------------------------------------------
__device__ __forceinline__ uint32_t smem_u32(const void* p) {
    uint32_t a;
    asm("{ .reg .u64 t; cvta.to.shared.u64 t, %1; cvt.u32.u64 %0, t; }" : "=r"(a) : "l"(p));
    return a;
}
__device__ __forceinline__ void ldsm4(uint32_t r[4], uint32_t addr) {
    asm volatile("ldmatrix.sync.aligned.m8n8.x4.shared.b16 {%0,%1,%2,%3}, [%4];"
                 : "=r"(r[0]), "=r"(r[1]), "=r"(r[2]), "=r"(r[3]) : "r"(addr));
}
// fp16-accumulate HMMA
__device__ __forceinline__ void mma16816h(uint32_t c[2], const uint32_t a[4], const uint32_t b[2]) {
    asm volatile("mma.sync.aligned.m16n8k16.row.col.f16.f16.f16.f16 "
                 "{%0,%1}, {%2,%3,%4,%5}, {%6,%7}, {%0,%1};"
                 : "+r"(c[0]), "+r"(c[1])
                 : "r"(a[0]), "r"(a[1]), "r"(a[2]), "r"(a[3]), "r"(b[0]), "r"(b[1]));
}
__device__ __forceinline__ uint32_t packh(__half a, __half b) {
    __half2 t = __halves2half2(a, b);
    uint32_t r; memcpy(&r, &t, 4); return r;
}
__device__ __forceinline__ __half2 u2h2(uint32_t u) {
    __half2 h; memcpy(&h, &u, 4); return h;
}
__device__ __forceinline__ uint32_t h22u(__half2 h) {
    uint32_t u; memcpy(&u, &h, 4); return u;
}
#define GBAR(id) asm volatile("bar.sync %0, %1;" :: "r"(id), "r"(256) : "memory")

// ------------------------------------------------------------------
// Weight prep: transpose to [n][k], convert to fp16; also zero g_agg
// ------------------------------------------------------------------
__global__ void prep_weights(const float* __restrict__ lW1,
                             const float* __restrict__ lW2,
                             const float* __restrict__ lW3) {
    int i = blockIdx.x * 256 + threadIdx.x;
    if (i < 8192)       { int n = i >> 6, k = i & 63;
                          g_w1[i] = __float2half_rn((k < 32) ? lW1[k * 128 + n] : 0.0f); }
    else if (i < 24576) { int e = i - 8192;  int n = e >> 7, k = e & 127;
                          g_w2[e] = __float2half_rn(lW2[k * 128 + n]); }
    else if (i < 40960) { int e = i - 24576; int n = e >> 7, k = e & 127;
                          g_w3[e] = __float2half_rn(lW3[k * 128 + n]); }
    for (int j = i; j < NSEG * EMB; j += 160 * 256) g_agg[j] = 0.0f;
}

// ------------------------------------------------------------------
// Local MLP: persistent HMMA kernel (fp16 acc), two 256-thread groups
// smem layout (byte offsets from 1024-aligned base)
// ------------------------------------------------------------------
#define OFF_W1  0          /* [128][pitch 80B], k<32 used : 10240 */
#define OFF_W2  10240      /* [128][256B] swizzled : 32768 */
#define OFF_W3  43008
#define OFF_GRP 75776      /* per-group: P0 (32768) + P1 (32768) */
#define OFF_B1  206848     /* half2[64] per layer */
#define OFF_B2  207360
#define OFF_B3  207872
#define OFF_IDX 208384     /* per group: 2 x 128 ints (ping-pong), 1024B each */
#define DYN_BYTES (210432 + 1024)

// Single-pass fp16-acc GEMM per group: D += A * W.  M=128 x N=128 x K=16*KSTEPS.
// 8 warps/group: wm = (gwid>>2)*64 (4 m16 frags), wn = (gwid&3)*32.
template<int KSTEPS, bool ISW1>
__device__ __forceinline__ void gemm1(uint32_t aB, uint32_t wB,
                                      uint32_t acc[4][4][2], int wm, int wn, int lane) {
    const int r  = lane & 7;
    const int hs = (lane >> 3) & 1;
    const int qs = (lane >> 4) & 1;
    int am[4];
#pragma unroll
    for (int f = 0; f < 4; ++f) am[f] = (wm + f * 16 + r + hs * 8) * 256;
    const int bn0 = wn + r + qs * 8;
    const int bn1 = bn0 + 16;

#pragma unroll
    for (int ks = 0; ks < KSTEPS; ++ks) {
        const int ka = (ks * 16 + qs * 8) * 2;
        const int kb = (ks * 16 + hs * 8) * 2;
        uint32_t a[4][4], bq0[4], bq1[4];
        if (ISW1) {
            ldsm4(bq0, wB + bn0 * 80 + kb);
            ldsm4(bq1, wB + bn1 * 80 + kb);
        } else {
            ldsm4(bq0, wB + SWB(bn0 * 256 + kb));
            ldsm4(bq1, wB + SWB(bn1 * 256 + kb));
        }
#pragma unroll
        for (int f = 0; f < 4; ++f) ldsm4(a[f], aB + SWB(am[f] + ka));
#pragma unroll
        for (int f = 0; f < 4; ++f) {
            mma16816h(acc[f][0], a[f], bq0 + 0);
            mma16816h(acc[f][1], a[f], bq0 + 2);
            mma16816h(acc[f][2], a[f], bq1 + 0);
            mma16816h(acc[f][3], a[f], bq1 + 2);
        }
    }
}

__device__ __forceinline__ void zacc(uint32_t acc[4][4][2]) {
#pragma unroll
    for (int i = 0; i < 4; ++i)
#pragma unroll
        for (int j = 0; j < 4; ++j) { acc[i][j][0] = 0u; acc[i][j][1] = 0u; }
}

// bias (+optional relu) -> fp16 buffer (swizzled, 256B pitch)
template<bool RELU>
__device__ __forceinline__ void epi(uint32_t acc[4][4][2], char* wb, uint32_t offD,
                                    const uint32_t* bias2, int wm, int wn, int lane) {
    const int mr  = wm + (lane >> 2);
    const int nc0 = wn + 2 * (lane & 3);
    const __half2 z2 = __float2half2_rn(0.0f);
#pragma unroll
    for (int f = 0; f < 4; ++f)
#pragma unroll
        for (int nt = 0; nt < 4; ++nt) {
            const int n = nc0 + nt * 8;
            const __half2 b2 = u2h2(bias2[n >> 1]);
#pragma unroll
            for (int h = 0; h < 2; ++h) {
                const int m = mr + f * 16 + h * 8;
                __half2 v = __hadd2(u2h2(acc[f][nt][h]), b2);
                if (RELU) v = __hmax2(v, z2);
                *(uint32_t*)(wb + offD + SWB((uint32_t)(m * 256 + n * 2))) = h22u(v);
            }
        }
}

__global__ __launch_bounds__(512, 1)
void local_mlp_hmma(const float* __restrict__ x, const int* __restrict__ index,
                    const float* __restrict__ lb1, const float* __restrict__ lb2,
                    const float* __restrict__ lb3) {
    extern __shared__ char dsm[];
    char* wb = (char*)(((uintptr_t)dsm + 1023) & ~(uintptr_t)1023);
    const uint32_t wb32 = smem_u32(wb);

    const int tid  = threadIdx.x;
    const int gid  = tid >> 8;          // worker group 0/1
    const int gtid = tid & 255;
    const int gwid = gtid >> 5;         // warp within group (0..7)
    const int lane = tid & 31;
    const int wm   = (gwid >> 2) * 64;
    const int wn   = (gwid & 3) * 32;
    const int gbar = 1 + gid;           // named barrier id

    // ---- stage weights once per CTA (all 512 threads) ----
    for (int e = tid; e < 2048; e += 512) {     // W2/W3: 16B chunks
        int n = e >> 4, k0 = (e & 15) * 8;
        uint32_t off = (uint32_t)SWB(n * 256 + k0 * 2);
        *(uint4*)(wb + OFF_W2 + off) = *(const uint4*)(g_w2 + n * 128 + k0);
        *(uint4*)(wb + OFF_W3 + off) = *(const uint4*)(g_w3 + n * 128 + k0);
    }
    for (int e = tid; e < 1024; e += 512) {     // W1: pitch 80B, 8B chunks
        int n = e >> 3, k0 = (e & 7) * 4;
        *(uint2*)(wb + OFF_W1 + (uint32_t)(n * 80 + k0 * 2)) =
            *(const uint2*)(g_w1 + n * 64 + k0);
    }
    uint32_t* sB1 = (uint32_t*)(wb + OFF_B1);
    uint32_t* sB2 = (uint32_t*)(wb + OFF_B2);
    uint32_t* sB3 = (uint32_t*)(wb + OFF_B3);
    if (tid < 64) {
        sB1[tid] = packh(__float2half_rn(lb1[2 * tid]), __float2half_rn(lb1[2 * tid + 1]));
        sB2[tid] = packh(__float2half_rn(lb2[2 * tid]), __float2half_rn(lb2[2 * tid + 1]));
        sB3[tid] = packh(__float2half_rn(lb3[2 * tid]), __float2half_rn(lb3[2 * tid + 1]));
    }
    __syncthreads();

    // per-group buffers
    char* gb = wb + OFF_GRP + gid * 65536;
    const uint32_t P0off = (uint32_t)(OFF_GRP + gid * 65536);
    const uint32_t P1off = P0off + 32768;
    const uint32_t P0 = wb32 + P0off, P1 = wb32 + P1off;
    int* sIdx0 = (int*)(wb + OFF_IDX + gid * 1024);
    int* sIdx1 = sIdx0 + 128;
    const uint32_t W1 = wb32 + OFF_W1, W2 = wb32 + OFF_W2, W3 = wb32 + OFF_W3;

    // x staging coords: each thread handles half a row (16 floats)
    const int xm = gtid >> 1;
    const int xc = (gtid & 1) * 16;
    const int stride = 2 * gridDim.x;

    uint32_t acc[4][4][2];
    float4 f4[4];
    int idxn = 0;
    int pp = 0;

    // ---- prologue: load + stage first tile; prefetch second ----
    {
        const int t0 = blockIdx.x * 2 + gid;
        const size_t v0 = (size_t)t0 * TILE_M;
        const float4* xr = (const float4*)(x + (v0 + xm) * NCAND + xc);
#pragma unroll
        for (int q = 0; q < 4; ++q) f4[q] = xr[q];
        uint4 h0 = make_uint4(
            packh(__float2half_rn(f4[0].x), __float2half_rn(f4[0].y)),
            packh(__float2half_rn(f4[0].z), __float2half_rn(f4[0].w)),
            packh(__float2half_rn(f4[1].x), __float2half_rn(f4[1].y)),
            packh(__float2half_rn(f4[1].z), __float2half_rn(f4[1].w)));
        uint4 h1 = make_uint4(
            packh(__float2half_rn(f4[2].x), __float2half_rn(f4[2].y)),
            packh(__float2half_rn(f4[2].z), __float2half_rn(f4[2].w)),
            packh(__float2half_rn(f4[3].x), __float2half_rn(f4[3].y)),
            packh(__float2half_rn(f4[3].z), __float2half_rn(f4[3].w)));
        uint32_t base = (uint32_t)(xm * 256 + xc * 2);
        *(uint4*)(gb + SWB(base))      = h0;
        *(uint4*)(gb + SWB(base + 16)) = h1;
        if (gtid < TILE_M) sIdx0[gtid] = index[v0 + gtid];
        // prefetch second tile
        const int t1 = t0 + stride;
        if (t1 < NTILES) {
            const size_t v1 = (size_t)t1 * TILE_M;
            const float4* xr1 = (const float4*)(x + (v1 + xm) * NCAND + xc);
#pragma unroll
            for (int q = 0; q < 4; ++q) f4[q] = xr1[q];
            if (gtid < TILE_M) idxn = index[v1 + gtid];
        }
    }
    GBAR(gbar);

    for (int t = blockIdx.x * 2 + gid; t < NTILES; t += stride) {
        // ---- L1: relu(x @ W1 + b1) -> P1 ----
        zacc(acc);
        gemm1<2, true>(P0, W1, acc, wm, wn, lane);
        epi<true>(acc, wb, P1off, sB1, wm, wn, lane);
        GBAR(gbar);

        // ---- L2: relu(h1 @ W2 + b2) -> P0 ----
        zacc(acc);
        gemm1<8, false>(P1, W2, acc, wm, wn, lane);
        epi<true>(acc, wb, P0off, sB2, wm, wn, lane);
        GBAR(gbar);

        // ---- L3: h2 @ W3 (bias folded during reduce) ----
        zacc(acc);
        gemm1<8, false>(P0, W3, acc, wm, wn, lane);
        GBAR(gbar);   // P0 reads done -> safe to restage

        // ---- stage NEXT tile's x -> P0 ----
        const int tn = t + stride;
        int* sIdxC = pp ? sIdx1 : sIdx0;
        int* sIdxN = pp ? sIdx0 : sIdx1;
        if (tn < NTILES) {
            uint4 h0 = make_uint4(
                packh(__float2half_rn(f4[0].x), __float2half_rn(f4[0].y)),
                packh(__float2half_rn(f4[0].z), __float2half_rn(f4[0].w)),
                packh(__float2half_rn(f4[1].x), __float2half_rn(f4[1].y)),
                packh(__float2half_rn(f4[1].z), __float2half_rn(f4[1].w)));
            uint4 h1 = make_uint4(
                packh(__float2half_rn(f4[2].x), __float2half_rn(f4[2].y)),
                packh(__float2half_rn(f4[2].z), __float2half_rn(f4[2].w)),
                packh(__float2half_rn(f4[3].x), __float2half_rn(f4[3].y)),
                packh(__float2half_rn(f4[3].z), __float2half_rn(f4[3].w)));
            uint32_t base = (uint32_t)(xm * 256 + xc * 2);
            *(uint4*)(gb + SWB(base))      = h0;
            *(uint4*)(gb + SWB(base + 16)) = h1;
            if (gtid < TILE_M) sIdxN[gtid] = idxn;
        }

        // ---- register-direct segment reduce of L3 acc + bias ----
        {
            const int s0 = sIdxC[wm];
            const int s1 = sIdxC[wm + 63];
            if (s0 == s1) {
                // fast path (~77% of warps): warp's 64-row span is one segment
                float2 s[4];
#pragma unroll
                for (int nt = 0; nt < 4; ++nt) {
                    float sx = 0.f, sy = 0.f;
#pragma unroll
                    for (int f = 0; f < 4; ++f)
#pragma unroll
                        for (int h = 0; h < 2; ++h) {
                            float2 v = __half22float2(u2h2(acc[f][nt][h]));
                            sx += v.x; sy += v.y;
                        }
                    const int n = wn + 2 * (lane & 3) + nt * 8;
                    float2 b = __half22float2(u2h2(sB3[n >> 1]));
                    s[nt].x = sx + 8.0f * b.x;
                    s[nt].y = sy + 8.0f * b.y;
                }
                // reduce across the 8 row-lanes (stride-4 lane groups)
#pragma unroll
                for (int mask = 4; mask <= 16; mask <<= 1)
#pragma unroll
                    for (int nt = 0; nt < 4; ++nt) {
                        s[nt].x += __shfl_xor_sync(0xffffffffu, s[nt].x, mask);
                        s[nt].y += __shfl_xor_sync(0xffffffffu, s[nt].y, mask);
                    }
                if (lane < 4) {
                    float* dst = &g_agg[s0 * EMB + wn + 2 * lane];
#pragma unroll
                    for (int nt = 0; nt < 4; ++nt) {
                        atomicAdd(dst + nt * 8,     s[nt].x);
                        atomicAdd(dst + nt * 8 + 1, s[nt].y);
                    }
                }
            } else {
                // slow path: spill warp's block to P1 (with bias), scalar flush
                epi<false>(acc, wb, P1off, sB3, wm, wn, lane);
                __syncwarp();
                const int col = wn + lane;
                int cur = s0;
                float s = 0.0f;
                for (int r = 0; r < 64; ++r) {
                    const int row = wm + r;
                    int ix = sIdxC[row];
                    if (ix != cur) {
                        atomicAdd(&g_agg[cur * EMB + col], s);
                        s = 0.0f; cur = ix;
                    }
                    s += __half2float(*(const __half*)(gb + 32768 +
                            SWB((uint32_t)(row * 256 + col * 2))));
                }
                atomicAdd(&g_agg[cur * EMB + col], s);
            }
        }

        // ---- prefetch tile t+2*stride (consumed at next stage) ----
        const int tn2 = t + 2 * stride;
        if (tn2 < NTILES) {
            const size_t v2 = (size_t)tn2 * TILE_M;
            const float4* xr = (const float4*)(x + (v2 + xm) * NCAND + xc);
#pragma unroll
            for (int q = 0; q < 4; ++q) f4[q] = xr[q];
            if (gtid < TILE_M) idxn = index[v2 + gtid];
        }
        GBAR(gbar);
        pp ^= 1;
    }
}

// ------------------------------------------------------------------
// Global MLP: 256 CTAs x 16 segments — each weight LDG reused 16x
// ------------------------------------------------------------------
__global__ __launch_bounds__(128)
void global_mlp_kernel(const float* __restrict__ gW1, const float* __restrict__ gb1,
                       const float* __restrict__ gW2, const float* __restrict__ gb2,
                       const float* __restrict__ gW3, const float* __restrict__ gb3,
                       float* __restrict__ out) {
    __shared__ float sIn[16][EMB];
    __shared__ float sH[16][EMB];
    __shared__ float sG[16][EMB];
    const int tid = threadIdx.x;
    const int seg0 = blockIdx.x * 16;

#pragma unroll
    for (int j = 0; j < 16; ++j) sIn[j][tid] = g_agg[(seg0 + j) * EMB + tid];
    __syncthreads();

    // layer g1: 16 segments share each weight load
    {
        const float b1 = __ldg(&gb1[tid]);
        float a[16];
#pragma unroll
        for (int j = 0; j < 16; ++j) a[j] = 0.f;
#pragma unroll 2
        for (int k = 0; k < EMB; ++k) {
            const float w = __ldg(&gW1[k * EMB + tid]);
#pragma unroll
            for (int j = 0; j < 16; ++j) a[j] += sIn[j][k] * w;
        }
#pragma unroll
        for (int j = 0; j < 16; ++j) sH[j][tid] = fmaxf(a[j] + b1, 0.0f);
    }
    __syncthreads();

    // layer g2
    {
        const float b2 = __ldg(&gb2[tid]);
        float a[16];
#pragma unroll
        for (int j = 0; j < 16; ++j) a[j] = 0.f;
#pragma unroll 2
        for (int k = 0; k < EMB; ++k) {
            const float w = __ldg(&gW2[k * EMB + tid]);
#pragma unroll
            for (int j = 0; j < 16; ++j) a[j] += sH[j][k] * w;
        }
#pragma unroll
        for (int j = 0; j < 16; ++j) sG[j][tid] = fmaxf(a[j] + b2, 0.0f);
    }
    __syncthreads();

    // layer g3 + log_softmax: warp w handles segments seg0+w+4*rot
    {
        const int c = tid & 31;
        const float b3 = __ldg(&gb3[c]);
#pragma unroll
        for (int rot = 0; rot < 4; ++rot) {
            const int j = (tid >> 5) + rot * 4;
            float s0 = 0.f, s1 = 0.f, s2 = 0.f, s3 = 0.f;
#pragma unroll 8
            for (int k = 0; k < EMB; k += 4) {
                s0 += sG[j][k]     * __ldg(&gW3[(k)     * NCAND + c]);
                s1 += sG[j][k + 1] * __ldg(&gW3[(k + 1) * NCAND + c]);
                s2 += sG[j][k + 2] * __ldg(&gW3[(k + 2) * NCAND + c]);
                s3 += sG[j][k + 3] * __ldg(&gW3[(k + 3) * NCAND + c]);
            }
            float sc = (s0 + s1) + (s2 + s3) + b3;
            float mx = sc;
#pragma unroll
            for (int o = 16; o > 0; o >>= 1) mx = fmaxf(mx, __shfl_xor_sync(0xffffffffu, mx, o));
            float e = expf(sc - mx);
            float ssum = e;
#pragma unroll
            for (int o = 16; o > 0; o >>= 1) ssum += __shfl_xor_sync(0xffffffffu, ssum, o);
            out[(seg0 + j) * NCAND + c] = sc - mx - logf(ssum);
        }
    }
}

extern "C" void kernel_launch(void* const* d_in, const int* in_sizes, int n_in,
                              void* d_out, int out_size) {
    const float* x     = (const float*)d_in[0];
    const int*   index = (const int*)d_in[1];
    const float* lW1 = (const float*)d_in[2];
    const float* lb1 = (const float*)d_in[3];
    const float* lW2 = (const float*)d_in[4];
    const float* lb2 = (const float*)d_in[5];
    const float* lW3 = (const float*)d_in[6];
    const float* lb3 = (const float*)d_in[7];
    const float* gW1 = (const float*)d_in[8];
    const float* gb1 = (const float*)d_in[9];
    const float* gW2 = (const float*)d_in[10];
    const float* gb2 = (const float*)d_in[11];
    const float* gW3 = (const float*)d_in[12];
    const float* gb3 = (const float*)d_in[13];
    float* out = (float*)d_out;

    cudaFuncSetAttribute(local_mlp_hmma,
                         cudaFuncAttributeMaxDynamicSharedMemorySize, DYN_BYTES);

    prep_weights<<<160, 256>>>(lW1, lW2, lW3);
    local_mlp_hmma<<<148, 512, DYN_BYTES>>>(x, index, lb1, lb2, lb3);
    global_mlp_kernel<<<NSEG / 16, 128>>>(gW1, gb1, gW2, gb2, gW3, gb3, out);
}

// round 15
// speedup vs baseline: 1.0975x; 1.0975x over previous
#include <cuda_runtime.h>
#include <cuda_fp16.h>
#include <cstdint>
#include <cstring>
#include <math.h>

#define NSEG   4096
#define NVOT   1048576
#define NCAND  32
#define EMB    128
#define TILE_M 128
#define NTILES (NVOT / TILE_M)   // 8192

// 256B-pitch shared-tile swizzle: XOR 16B-unit index with row low bits
#define SWB(o) ((o) ^ (((o) >> 4) & 0x70))

// ------------------------------------------------------------------
// Device scratch (allocation-free rule: __device__ globals)
// ------------------------------------------------------------------
__device__ float g_agg[NSEG * EMB];
__device__ __half g_w1[128 * 64];
__device__ __half g_w2[128 * 128];
__device__ __half g_w3[128 * 128];

// ------------------------------------------------------------------
// PTX helpers (sm_80-era: legal in compute_103 PTX)
// ------------------------------------------------------------------
__device__ __forceinline__ uint32_t smem_u32(const void* p) {
    uint32_t a;
    asm("{ .reg .u64 t; cvta.to.shared.u64 t, %1; cvt.u32.u64 %0, t; }" : "=r"(a) : "l"(p));
    return a;
}
__device__ __forceinline__ void ldsm4(uint32_t r[4], uint32_t addr) {
    asm volatile("ldmatrix.sync.aligned.m8n8.x4.shared.b16 {%0,%1,%2,%3}, [%4];"
                 : "=r"(r[0]), "=r"(r[1]), "=r"(r[2]), "=r"(r[3]) : "r"(addr));
}
// fp16-accumulate HMMA
__device__ __forceinline__ void mma16816h(uint32_t c[2], const uint32_t a[4], const uint32_t b[2]) {
    asm volatile("mma.sync.aligned.m16n8k16.row.col.f16.f16.f16.f16 "
                 "{%0,%1}, {%2,%3,%4,%5}, {%6,%7}, {%0,%1};"
                 : "+r"(c[0]), "+r"(c[1])
                 : "r"(a[0]), "r"(a[1]), "r"(a[2]), "r"(a[3]), "r"(b[0]), "r"(b[1]));
}
__device__ __forceinline__ uint32_t packh(__half a, __half b) {
    __half2 t = __halves2half2(a, b);
    uint32_t r; memcpy(&r, &t, 4); return r;
}
__device__ __forceinline__ __half2 u2h2(uint32_t u) {
    __half2 h; memcpy(&h, &u, 4); return h;
}
__device__ __forceinline__ uint32_t h22u(__half2 h) {
    uint32_t u; memcpy(&u, &h, 4); return u;
}
#define GBAR(id) asm volatile("bar.sync %0, %1;" :: "r"(id), "r"(256) : "memory")

// ------------------------------------------------------------------
// Weight prep: transpose to [n][k], convert to fp16; also zero g_agg
// ------------------------------------------------------------------
__global__ void prep_weights(const float* __restrict__ lW1,
                             const float* __restrict__ lW2,
                             const float* __restrict__ lW3) {
    int i = blockIdx.x * 256 + threadIdx.x;
    if (i < 8192)       { int n = i >> 6, k = i & 63;
                          g_w1[i] = __float2half_rn((k < 32) ? lW1[k * 128 + n] : 0.0f); }
    else if (i < 24576) { int e = i - 8192;  int n = e >> 7, k = e & 127;
                          g_w2[e] = __float2half_rn(lW2[k * 128 + n]); }
    else if (i < 40960) { int e = i - 24576; int n = e >> 7, k = e & 127;
                          g_w3[e] = __float2half_rn(lW3[k * 128 + n]); }
    for (int j = i; j < NSEG * EMB; j += 160 * 256) g_agg[j] = 0.0f;
}

// ------------------------------------------------------------------
// Local MLP: persistent HMMA kernel (fp16 acc), two 256-thread groups
// smem layout (byte offsets from 1024-aligned base)
// ------------------------------------------------------------------
#define OFF_W1  0          /* [128][pitch 80B], k<32 used : 10240 */
#define OFF_W2  10240      /* [128][256B] swizzled : 32768 */
#define OFF_W3  43008
#define OFF_GRP 75776      /* per-group: P0 (32768) + P1 (32768) */
#define OFF_B1  206848     /* half2[64] per layer */
#define OFF_B2  207360
#define OFF_B3  207872
#define OFF_IDX 208384     /* per group: 2 x 128 ints (ping-pong), 1024B each */
#define DYN_BYTES (210432 + 1024)

// Single-pass fp16-acc GEMM per group: D += A * W.  M=128 x N=128 x K=16*KSTEPS.
// 8 warps/group: wm = (gwid>>2)*64 (4 m16 frags), wn = (gwid&3)*32.
template<int KSTEPS, bool ISW1>
__device__ __forceinline__ void gemm1(uint32_t aB, uint32_t wB,
                                      uint32_t acc[4][4][2], int wm, int wn, int lane) {
    const int r  = lane & 7;
    const int hs = (lane >> 3) & 1;
    const int qs = (lane >> 4) & 1;
    int am[4];
#pragma unroll
    for (int f = 0; f < 4; ++f) am[f] = (wm + f * 16 + r + hs * 8) * 256;
    const int bn0 = wn + r + qs * 8;
    const int bn1 = bn0 + 16;

#pragma unroll
    for (int ks = 0; ks < KSTEPS; ++ks) {
        const int ka = (ks * 16 + qs * 8) * 2;
        const int kb = (ks * 16 + hs * 8) * 2;
        uint32_t a[4][4], bq0[4], bq1[4];
        if (ISW1) {
            ldsm4(bq0, wB + bn0 * 80 + kb);
            ldsm4(bq1, wB + bn1 * 80 + kb);
        } else {
            ldsm4(bq0, wB + SWB(bn0 * 256 + kb));
            ldsm4(bq1, wB + SWB(bn1 * 256 + kb));
        }
#pragma unroll
        for (int f = 0; f < 4; ++f) ldsm4(a[f], aB + SWB(am[f] + ka));
#pragma unroll
        for (int f = 0; f < 4; ++f) {
            mma16816h(acc[f][0], a[f], bq0 + 0);
            mma16816h(acc[f][1], a[f], bq0 + 2);
            mma16816h(acc[f][2], a[f], bq1 + 0);
            mma16816h(acc[f][3], a[f], bq1 + 2);
        }
    }
}

__device__ __forceinline__ void zacc(uint32_t acc[4][4][2]) {
#pragma unroll
    for (int i = 0; i < 4; ++i)
#pragma unroll
        for (int j = 0; j < 4; ++j) { acc[i][j][0] = 0u; acc[i][j][1] = 0u; }
}

// bias (+optional relu) -> fp16 buffer (swizzled, 256B pitch)
template<bool RELU>
__device__ __forceinline__ void epi(uint32_t acc[4][4][2], char* wb, uint32_t offD,
                                    const uint32_t* bias2, int wm, int wn, int lane) {
    const int mr  = wm + (lane >> 2);
    const int nc0 = wn + 2 * (lane & 3);
    const __half2 z2 = __float2half2_rn(0.0f);
#pragma unroll
    for (int f = 0; f < 4; ++f)
#pragma unroll
        for (int nt = 0; nt < 4; ++nt) {
            const int n = nc0 + nt * 8;
            const __half2 b2 = u2h2(bias2[n >> 1]);
#pragma unroll
            for (int h = 0; h < 2; ++h) {
                const int m = mr + f * 16 + h * 8;
                __half2 v = __hadd2(u2h2(acc[f][nt][h]), b2);
                if (RELU) v = __hmax2(v, z2);
                *(uint32_t*)(wb + offD + SWB((uint32_t)(m * 256 + n * 2))) = h22u(v);
            }
        }
}

__global__ __launch_bounds__(512, 1)
void local_mlp_hmma(const float* __restrict__ x, const int* __restrict__ index,
                    const float* __restrict__ lb1, const float* __restrict__ lb2,
                    const float* __restrict__ lb3) {
    extern __shared__ char dsm[];
    char* wb = (char*)(((uintptr_t)dsm + 1023) & ~(uintptr_t)1023);
    const uint32_t wb32 = smem_u32(wb);

    const int tid  = threadIdx.x;
    const int gid  = tid >> 8;          // worker group 0/1
    const int gtid = tid & 255;
    const int gwid = gtid >> 5;         // warp within group (0..7)
    const int lane = tid & 31;
    const int wm   = (gwid >> 2) * 64;
    const int wn   = (gwid & 3) * 32;
    const int gbar = 1 + gid;           // named barrier id

    // ---- stage weights once per CTA (all 512 threads) ----
    for (int e = tid; e < 2048; e += 512) {     // W2/W3: 16B chunks
        int n = e >> 4, k0 = (e & 15) * 8;
        uint32_t off = (uint32_t)SWB(n * 256 + k0 * 2);
        *(uint4*)(wb + OFF_W2 + off) = *(const uint4*)(g_w2 + n * 128 + k0);
        *(uint4*)(wb + OFF_W3 + off) = *(const uint4*)(g_w3 + n * 128 + k0);
    }
    for (int e = tid; e < 1024; e += 512) {     // W1: pitch 80B, 8B chunks
        int n = e >> 3, k0 = (e & 7) * 4;
        *(uint2*)(wb + OFF_W1 + (uint32_t)(n * 80 + k0 * 2)) =
            *(const uint2*)(g_w1 + n * 64 + k0);
    }
    uint32_t* sB1 = (uint32_t*)(wb + OFF_B1);
    uint32_t* sB2 = (uint32_t*)(wb + OFF_B2);
    uint32_t* sB3 = (uint32_t*)(wb + OFF_B3);
    if (tid < 64) {
        sB1[tid] = packh(__float2half_rn(lb1[2 * tid]), __float2half_rn(lb1[2 * tid + 1]));
        sB2[tid] = packh(__float2half_rn(lb2[2 * tid]), __float2half_rn(lb2[2 * tid + 1]));
        sB3[tid] = packh(__float2half_rn(lb3[2 * tid]), __float2half_rn(lb3[2 * tid + 1]));
    }
    __syncthreads();

    // per-group buffers
    char* gb = wb + OFF_GRP + gid * 65536;
    const uint32_t P0off = (uint32_t)(OFF_GRP + gid * 65536);
    const uint32_t P1off = P0off + 32768;
    const uint32_t P0 = wb32 + P0off, P1 = wb32 + P1off;
    int* sIdx0 = (int*)(wb + OFF_IDX + gid * 1024);
    int* sIdx1 = sIdx0 + 128;
    const uint32_t W1 = wb32 + OFF_W1, W2 = wb32 + OFF_W2, W3 = wb32 + OFF_W3;

    // x staging coords: each thread handles half a row (16 floats)
    const int xm = gtid >> 1;
    const int xc = (gtid & 1) * 16;
    const int stride = 2 * gridDim.x;

    uint32_t acc[4][4][2];
    float4 f4[4];
    int idxn = 0;
    int pp = 0;

    // ---- prologue: load + stage first tile; prefetch second ----
    {
        const int t0 = blockIdx.x * 2 + gid;
        const size_t v0 = (size_t)t0 * TILE_M;
        const float4* xr = (const float4*)(x + (v0 + xm) * NCAND + xc);
#pragma unroll
        for (int q = 0; q < 4; ++q) f4[q] = xr[q];
        uint4 h0 = make_uint4(
            packh(__float2half_rn(f4[0].x), __float2half_rn(f4[0].y)),
            packh(__float2half_rn(f4[0].z), __float2half_rn(f4[0].w)),
            packh(__float2half_rn(f4[1].x), __float2half_rn(f4[1].y)),
            packh(__float2half_rn(f4[1].z), __float2half_rn(f4[1].w)));
        uint4 h1 = make_uint4(
            packh(__float2half_rn(f4[2].x), __float2half_rn(f4[2].y)),
            packh(__float2half_rn(f4[2].z), __float2half_rn(f4[2].w)),
            packh(__float2half_rn(f4[3].x), __float2half_rn(f4[3].y)),
            packh(__float2half_rn(f4[3].z), __float2half_rn(f4[3].w)));
        uint32_t base = (uint32_t)(xm * 256 + xc * 2);
        *(uint4*)(gb + SWB(base))      = h0;
        *(uint4*)(gb + SWB(base + 16)) = h1;
        if (gtid < TILE_M) sIdx0[gtid] = index[v0 + gtid];
        // prefetch second tile
        const int t1 = t0 + stride;
        if (t1 < NTILES) {
            const size_t v1 = (size_t)t1 * TILE_M;
            const float4* xr1 = (const float4*)(x + (v1 + xm) * NCAND + xc);
#pragma unroll
            for (int q = 0; q < 4; ++q) f4[q] = xr1[q];
            if (gtid < TILE_M) idxn = index[v1 + gtid];
        }
    }
    GBAR(gbar);

    for (int t = blockIdx.x * 2 + gid; t < NTILES; t += stride) {
        // ---- L1: relu(x @ W1 + b1) -> P1 ----
        zacc(acc);
        gemm1<2, true>(P0, W1, acc, wm, wn, lane);
        epi<true>(acc, wb, P1off, sB1, wm, wn, lane);
        GBAR(gbar);

        // ---- L2: relu(h1 @ W2 + b2) -> P0 ----
        zacc(acc);
        gemm1<8, false>(P1, W2, acc, wm, wn, lane);
        epi<true>(acc, wb, P0off, sB2, wm, wn, lane);
        GBAR(gbar);

        // ---- L3: h2 @ W3 + b3 -> P1 (fp16) ----
        zacc(acc);
        gemm1<8, false>(P0, W3, acc, wm, wn, lane);
        epi<false>(acc, wb, P1off, sB3, wm, wn, lane);
        GBAR(gbar);

        // ---- stage NEXT tile's x -> P0 (free: last read was L3) ----
        const int tn = t + stride;
        int* sIdxC = pp ? sIdx1 : sIdx0;
        int* sIdxN = pp ? sIdx0 : sIdx1;
        if (tn < NTILES) {
            uint4 h0 = make_uint4(
                packh(__float2half_rn(f4[0].x), __float2half_rn(f4[0].y)),
                packh(__float2half_rn(f4[0].z), __float2half_rn(f4[0].w)),
                packh(__float2half_rn(f4[1].x), __float2half_rn(f4[1].y)),
                packh(__float2half_rn(f4[1].z), __float2half_rn(f4[1].w)));
            uint4 h1 = make_uint4(
                packh(__float2half_rn(f4[2].x), __float2half_rn(f4[2].y)),
                packh(__float2half_rn(f4[2].z), __float2half_rn(f4[2].w)),
                packh(__float2half_rn(f4[3].x), __float2half_rn(f4[3].y)),
                packh(__float2half_rn(f4[3].z), __float2half_rn(f4[3].w)));
            uint32_t base = (uint32_t)(xm * 256 + xc * 2);
            *(uint4*)(gb + SWB(base))      = h0;
            *(uint4*)(gb + SWB(base + 16)) = h1;
            if (gtid < TILE_M) sIdxN[gtid] = idxn;
        }

        // ---- sorted-segment reduce from P1 (half2) -> fp32 global atomics ----
        // 256 threads: 32 col-quads x 8 row-chunks of 16.
        // Sorted index => chunk is single-segment iff first==last (94% of chunks).
        {
            const int quad  = gtid & 31;           // cols 4*quad .. 4*quad+3
            const int rbase = (gtid >> 5) * 16;
            const uint32_t cb = (uint32_t)(quad * 8);
            const int s0 = sIdxC[rbase];
            const int s1 = sIdxC[rbase + 15];
            float a0 = 0.f, a1 = 0.f, a2 = 0.f, a3 = 0.f;
            if (s0 == s1) {
                // fast path: branch-free sum of 16 rows
#pragma unroll
                for (int r = 0; r < 16; ++r) {
                    uint32_t off = SWB((uint32_t)((rbase + r) * 256) + cb);
                    uint2 u = *(const uint2*)(gb + 32768 + off);
                    float2 g0 = __half22float2(u2h2(u.x));
                    float2 g1 = __half22float2(u2h2(u.y));
                    a0 += g0.x; a1 += g0.y; a2 += g1.x; a3 += g1.y;
                }
                float* dst = &g_agg[s0 * EMB + quad * 4];
                atomicAdd(dst + 0, a0); atomicAdd(dst + 1, a1);
                atomicAdd(dst + 2, a2); atomicAdd(dst + 3, a3);
            } else {
                // slow path: per-row flush on boundary
                int cur = s0;
#pragma unroll 4
                for (int r = 0; r < 16; ++r) {
                    int ix = sIdxC[rbase + r];
                    if (ix != cur) {
                        float* dst = &g_agg[cur * EMB + quad * 4];
                        atomicAdd(dst + 0, a0); atomicAdd(dst + 1, a1);
                        atomicAdd(dst + 2, a2); atomicAdd(dst + 3, a3);
                        a0 = a1 = a2 = a3 = 0.f; cur = ix;
                    }
                    uint32_t off = SWB((uint32_t)((rbase + r) * 256) + cb);
                    uint2 u = *(const uint2*)(gb + 32768 + off);
                    float2 g0 = __half22float2(u2h2(u.x));
                    float2 g1 = __half22float2(u2h2(u.y));
                    a0 += g0.x; a1 += g0.y; a2 += g1.x; a3 += g1.y;
                }
                float* dst = &g_agg[cur * EMB + quad * 4];
                atomicAdd(dst + 0, a0); atomicAdd(dst + 1, a1);
                atomicAdd(dst + 2, a2); atomicAdd(dst + 3, a3);
            }
        }

        // ---- prefetch tile t+2*stride (consumed at next stage) ----
        const int tn2 = t + 2 * stride;
        if (tn2 < NTILES) {
            const size_t v2 = (size_t)tn2 * TILE_M;
            const float4* xr = (const float4*)(x + (v2 + xm) * NCAND + xc);
#pragma unroll
            for (int q = 0; q < 4; ++q) f4[q] = xr[q];
            if (gtid < TILE_M) idxn = index[v2 + gtid];
        }
        GBAR(gbar);
        pp ^= 1;
    }
}

// ------------------------------------------------------------------
// Global MLP: 256 CTAs x 16 segments — each weight LDG reused 16x
// ------------------------------------------------------------------
__global__ __launch_bounds__(128)
void global_mlp_kernel(const float* __restrict__ gW1, const float* __restrict__ gb1,
                       const float* __restrict__ gW2, const float* __restrict__ gb2,
                       const float* __restrict__ gW3, const float* __restrict__ gb3,
                       float* __restrict__ out) {
    __shared__ float sIn[16][EMB];
    __shared__ float sH[16][EMB];
    __shared__ float sG[16][EMB];
    const int tid = threadIdx.x;
    const int seg0 = blockIdx.x * 16;

#pragma unroll
    for (int j = 0; j < 16; ++j) sIn[j][tid] = g_agg[(seg0 + j) * EMB + tid];
    __syncthreads();

    // layer g1: 16 segments share each weight load
    {
        const float b1 = __ldg(&gb1[tid]);
        float a[16];
#pragma unroll
        for (int j = 0; j < 16; ++j) a[j] = 0.f;
#pragma unroll 2
        for (int k = 0; k < EMB; ++k) {
            const float w = __ldg(&gW1[k * EMB + tid]);
#pragma unroll
            for (int j = 0; j < 16; ++j) a[j] += sIn[j][k] * w;
        }
#pragma unroll
        for (int j = 0; j < 16; ++j) sH[j][tid] = fmaxf(a[j] + b1, 0.0f);
    }
    __syncthreads();

    // layer g2
    {
        const float b2 = __ldg(&gb2[tid]);
        float a[16];
#pragma unroll
        for (int j = 0; j < 16; ++j) a[j] = 0.f;
#pragma unroll 2
        for (int k = 0; k < EMB; ++k) {
            const float w = __ldg(&gW2[k * EMB + tid]);
#pragma unroll
            for (int j = 0; j < 16; ++j) a[j] += sH[j][k] * w;
        }
#pragma unroll
        for (int j = 0; j < 16; ++j) sG[j][tid] = fmaxf(a[j] + b2, 0.0f);
    }
    __syncthreads();

    // layer g3 + log_softmax: warp w handles segments seg0+w+4*rot
    {
        const int c = tid & 31;
        const float b3 = __ldg(&gb3[c]);
#pragma unroll
        for (int rot = 0; rot < 4; ++rot) {
            const int j = (tid >> 5) + rot * 4;
            float s0 = 0.f, s1 = 0.f, s2 = 0.f, s3 = 0.f;
#pragma unroll 8
            for (int k = 0; k < EMB; k += 4) {
                s0 += sG[j][k]     * __ldg(&gW3[(k)     * NCAND + c]);
                s1 += sG[j][k + 1] * __ldg(&gW3[(k + 1) * NCAND + c]);
                s2 += sG[j][k + 2] * __ldg(&gW3[(k + 2) * NCAND + c]);
                s3 += sG[j][k + 3] * __ldg(&gW3[(k + 3) * NCAND + c]);
            }
            float sc = (s0 + s1) + (s2 + s3) + b3;
            float mx = sc;
#pragma unroll
            for (int o = 16; o > 0; o >>= 1) mx = fmaxf(mx, __shfl_xor_sync(0xffffffffu, mx, o));
            float e = expf(sc - mx);
            float ssum = e;
#pragma unroll
            for (int o = 16; o > 0; o >>= 1) ssum += __shfl_xor_sync(0xffffffffu, ssum, o);
            out[(seg0 + j) * NCAND + c] = sc - mx - logf(ssum);
        }
    }
}

extern "C" void kernel_launch(void* const* d_in, const int* in_sizes, int n_in,
                              void* d_out, int out_size) {
    const float* x     = (const float*)d_in[0];
    const int*   index = (const int*)d_in[1];
    const float* lW1 = (const float*)d_in[2];
    const float* lb1 = (const float*)d_in[3];
    const float* lW2 = (const float*)d_in[4];
    const float* lb2 = (const float*)d_in[5];
    const float* lW3 = (const float*)d_in[6];
    const float* lb3 = (const float*)d_in[7];
    const float* gW1 = (const float*)d_in[8];
    const float* gb1 = (const float*)d_in[9];
    const float* gW2 = (const float*)d_in[10];
    const float* gb2 = (const float*)d_in[11];
    const float* gW3 = (const float*)d_in[12];
    const float* gb3 = (const float*)d_in[13];
    float* out = (float*)d_out;

    cudaFuncSetAttribute(local_mlp_hmma,
                         cudaFuncAttributeMaxDynamicSharedMemorySize, DYN_BYTES);

    prep_weights<<<160, 256>>>(lW1, lW2, lW3);
    local_mlp_hmma<<<148, 512, DYN_BYTES>>>(x, index, lb1, lb2, lb3);
    global_mlp_kernel<<<NSEG / 16, 128>>>(gW1, gb1, gW2, gb2, gW3, gb3, out);
}

// round 16
// speedup vs baseline: 1.1807x; 1.0758x over previous
#include <cuda_runtime.h>
#include <cuda_fp16.h>
#include <cstdint>
#include <cstring>
#include <math.h>

#define NSEG   4096
#define NVOT   1048576
#define NCAND  32
#define EMB    128
#define TILE_M 128
#define NTILES (NVOT / TILE_M)   // 8192

// 256B-pitch shared-tile swizzle: XOR 16B-unit index with row low bits
#define SWB(o) ((o) ^ (((o) >> 4) & 0x70))

// ------------------------------------------------------------------
// Device scratch (allocation-free rule: __device__ globals)
// ------------------------------------------------------------------
__device__ float g_agg[NSEG * EMB];
__device__ __half g_w1[128 * 64];
__device__ __half g_w2[128 * 128];
__device__ __half g_w3[128 * 128];

// ------------------------------------------------------------------
// PTX helpers (sm_80-era: legal in compute_103 PTX)
// ------------------------------------------------------------------
__device__ __forceinline__ uint32_t smem_u32(const void* p) {
    uint32_t a;
    asm("{ .reg .u64 t; cvta.to.shared.u64 t, %1; cvt.u32.u64 %0, t; }" : "=r"(a) : "l"(p));
    return a;
}
__device__ __forceinline__ void ldsm4(uint32_t r[4], uint32_t addr) {
    asm volatile("ldmatrix.sync.aligned.m8n8.x4.shared.b16 {%0,%1,%2,%3}, [%4];"
                 : "=r"(r[0]), "=r"(r[1]), "=r"(r[2]), "=r"(r[3]) : "r"(addr));
}
// fp16-accumulate HMMA
__device__ __forceinline__ void mma16816h(uint32_t c[2], const uint32_t a[4], const uint32_t b[2]) {
    asm volatile("mma.sync.aligned.m16n8k16.row.col.f16.f16.f16.f16 "
                 "{%0,%1}, {%2,%3,%4,%5}, {%6,%7}, {%0,%1};"
                 : "+r"(c[0]), "+r"(c[1])
                 : "r"(a[0]), "r"(a[1]), "r"(a[2]), "r"(a[3]), "r"(b[0]), "r"(b[1]));
}
__device__ __forceinline__ uint32_t packh(__half a, __half b) {
    __half2 t = __halves2half2(a, b);
    uint32_t r; memcpy(&r, &t, 4); return r;
}
__device__ __forceinline__ __half2 u2h2(uint32_t u) {
    __half2 h; memcpy(&h, &u, 4); return h;
}
__device__ __forceinline__ uint32_t h22u(__half2 h) {
    uint32_t u; memcpy(&u, &h, 4); return u;
}
#define GBAR(id) asm volatile("bar.sync %0, %1;" :: "r"(id), "r"(256) : "memory")

// ------------------------------------------------------------------
// Weight prep: transpose to [n][k], convert to fp16; also zero g_agg
// ------------------------------------------------------------------
__global__ void prep_weights(const float* __restrict__ lW1,
                             const float* __restrict__ lW2,
                             const float* __restrict__ lW3) {
    int i = blockIdx.x * 256 + threadIdx.x;
    if (i < 8192)       { int n = i >> 6, k = i & 63;
                          g_w1[i] = __float2half_rn((k < 32) ? lW1[k * 128 + n] : 0.0f); }
    else if (i < 24576) { int e = i - 8192;  int n = e >> 7, k = e & 127;
                          g_w2[e] = __float2half_rn(lW2[k * 128 + n]); }
    else if (i < 40960) { int e = i - 24576; int n = e >> 7, k = e & 127;
                          g_w3[e] = __float2half_rn(lW3[k * 128 + n]); }
    for (int j = i; j < NSEG * EMB; j += 160 * 256) g_agg[j] = 0.0f;
}

// ------------------------------------------------------------------
// Local MLP: persistent HMMA kernel (fp16 acc), two 256-thread groups
// smem layout (byte offsets from 1024-aligned base)
// ------------------------------------------------------------------
#define OFF_W1  0          /* [128][pitch 80B], k<32 used : 10240 */
#define OFF_W2  10240      /* [128][256B] swizzled : 32768 */
#define OFF_W3  43008
#define OFF_GRP 75776      /* per-group: P0 (32768) + P1 (32768) */
#define OFF_B1  206848     /* half2[64] per layer */
#define OFF_B2  207360
#define OFF_B3  207872
#define OFF_IDX 208384     /* per group: 2 x 128 ints (ping-pong), 1024B each */
#define DYN_BYTES (210432 + 1024)

// Single-pass fp16-acc GEMM per group: D += A * W.  M=128 x N=128 x K=16*KSTEPS.
// 8 warps/group: wm = (gwid>>2)*64 (4 m16 frags), wn = (gwid&3)*32.
template<int KSTEPS, bool ISW1>
__device__ __forceinline__ void gemm1(uint32_t aB, uint32_t wB,
                                      uint32_t acc[4][4][2], int wm, int wn, int lane) {
    const int r  = lane & 7;
    const int hs = (lane >> 3) & 1;
    const int qs = (lane >> 4) & 1;
    int am[4];
#pragma unroll
    for (int f = 0; f < 4; ++f) am[f] = (wm + f * 16 + r + hs * 8) * 256;
    const int bn0 = wn + r + qs * 8;
    const int bn1 = bn0 + 16;

#pragma unroll
    for (int ks = 0; ks < KSTEPS; ++ks) {
        const int ka = (ks * 16 + qs * 8) * 2;
        const int kb = (ks * 16 + hs * 8) * 2;
        uint32_t a[4][4], bq0[4], bq1[4];
        if (ISW1) {
            ldsm4(bq0, wB + bn0 * 80 + kb);
            ldsm4(bq1, wB + bn1 * 80 + kb);
        } else {
            ldsm4(bq0, wB + SWB(bn0 * 256 + kb));
            ldsm4(bq1, wB + SWB(bn1 * 256 + kb));
        }
#pragma unroll
        for (int f = 0; f < 4; ++f) ldsm4(a[f], aB + SWB(am[f] + ka));
#pragma unroll
        for (int f = 0; f < 4; ++f) {
            mma16816h(acc[f][0], a[f], bq0 + 0);
            mma16816h(acc[f][1], a[f], bq0 + 2);
            mma16816h(acc[f][2], a[f], bq1 + 0);
            mma16816h(acc[f][3], a[f], bq1 + 2);
        }
    }
}

// initialize accumulators with the layer bias (HMMA folds C=bias for free)
__device__ __forceinline__ void bini(uint32_t acc[4][4][2], const uint32_t* bias2,
                                     int wn, int lane) {
    const int nc0 = wn + 2 * (lane & 3);
#pragma unroll
    for (int nt = 0; nt < 4; ++nt) {
        const uint32_t b = bias2[(nc0 + nt * 8) >> 1];
#pragma unroll
        for (int f = 0; f < 4; ++f) { acc[f][nt][0] = b; acc[f][nt][1] = b; }
    }
}

// optional relu -> fp16 buffer (swizzled, 256B pitch); bias already in acc
template<bool RELU>
__device__ __forceinline__ void epi(uint32_t acc[4][4][2], char* wb, uint32_t offD,
                                    int wm, int wn, int lane) {
    const int mr  = wm + (lane >> 2);
    const int nc0 = wn + 2 * (lane & 3);
    const __half2 z2 = __float2half2_rn(0.0f);
#pragma unroll
    for (int f = 0; f < 4; ++f)
#pragma unroll
        for (int nt = 0; nt < 4; ++nt) {
            const int n = nc0 + nt * 8;
#pragma unroll
            for (int h = 0; h < 2; ++h) {
                const int m = mr + f * 16 + h * 8;
                __half2 v = u2h2(acc[f][nt][h]);
                if (RELU) v = __hmax2(v, z2);
                *(uint32_t*)(wb + offD + SWB((uint32_t)(m * 256 + n * 2))) = h22u(v);
            }
        }
}

__global__ __launch_bounds__(512, 1)
void local_mlp_hmma(const float* __restrict__ x, const int* __restrict__ index,
                    const float* __restrict__ lb1, const float* __restrict__ lb2,
                    const float* __restrict__ lb3) {
    extern __shared__ char dsm[];
    char* wb = (char*)(((uintptr_t)dsm + 1023) & ~(uintptr_t)1023);
    const uint32_t wb32 = smem_u32(wb);

    const int tid  = threadIdx.x;
    const int gid  = tid >> 8;          // worker group 0/1
    const int gtid = tid & 255;
    const int gwid = gtid >> 5;         // warp within group (0..7)
    const int lane = tid & 31;
    const int wm   = (gwid >> 2) * 64;
    const int wn   = (gwid & 3) * 32;
    const int gbar = 1 + gid;           // named barrier id

    // ---- stage weights once per CTA (all 512 threads) ----
    for (int e = tid; e < 2048; e += 512) {     // W2/W3: 16B chunks
        int n = e >> 4, k0 = (e & 15) * 8;
        uint32_t off = (uint32_t)SWB(n * 256 + k0 * 2);
        *(uint4*)(wb + OFF_W2 + off) = *(const uint4*)(g_w2 + n * 128 + k0);
        *(uint4*)(wb + OFF_W3 + off) = *(const uint4*)(g_w3 + n * 128 + k0);
    }
    for (int e = tid; e < 1024; e += 512) {     // W1: pitch 80B, 8B chunks
        int n = e >> 3, k0 = (e & 7) * 4;
        *(uint2*)(wb + OFF_W1 + (uint32_t)(n * 80 + k0 * 2)) =
            *(const uint2*)(g_w1 + n * 64 + k0);
    }
    uint32_t* sB1 = (uint32_t*)(wb + OFF_B1);
    uint32_t* sB2 = (uint32_t*)(wb + OFF_B2);
    uint32_t* sB3 = (uint32_t*)(wb + OFF_B3);
    if (tid < 64) {
        sB1[tid] = packh(__float2half_rn(lb1[2 * tid]), __float2half_rn(lb1[2 * tid + 1]));
        sB2[tid] = packh(__float2half_rn(lb2[2 * tid]), __float2half_rn(lb2[2 * tid + 1]));
        sB3[tid] = packh(__float2half_rn(lb3[2 * tid]), __float2half_rn(lb3[2 * tid + 1]));
    }
    __syncthreads();

    // per-group buffers
    char* gb = wb + OFF_GRP + gid * 65536;
    const uint32_t P0off = (uint32_t)(OFF_GRP + gid * 65536);
    const uint32_t P1off = P0off + 32768;
    const uint32_t P0 = wb32 + P0off, P1 = wb32 + P1off;
    int* sIdx0 = (int*)(wb + OFF_IDX + gid * 1024);
    int* sIdx1 = sIdx0 + 128;
    const uint32_t W1 = wb32 + OFF_W1, W2 = wb32 + OFF_W2, W3 = wb32 + OFF_W3;

    // x staging coords: each thread handles half a row (16 floats)
    const int xm = gtid >> 1;
    const int xc = (gtid & 1) * 16;
    const int stride = 2 * gridDim.x;

    uint32_t acc[4][4][2];
    float4 f4[4];
    int idxn = 0;
    int pp = 0;

    // ---- prologue: load + stage first tile; prefetch second ----
    {
        const int t0 = blockIdx.x * 2 + gid;
        const size_t v0 = (size_t)t0 * TILE_M;
        const float4* xr = (const float4*)(x + (v0 + xm) * NCAND + xc);
#pragma unroll
        for (int q = 0; q < 4; ++q) f4[q] = xr[q];
        uint4 h0 = make_uint4(
            packh(__float2half_rn(f4[0].x), __float2half_rn(f4[0].y)),
            packh(__float2half_rn(f4[0].z), __float2half_rn(f4[0].w)),
            packh(__float2half_rn(f4[1].x), __float2half_rn(f4[1].y)),
            packh(__float2half_rn(f4[1].z), __float2half_rn(f4[1].w)));
        uint4 h1 = make_uint4(
            packh(__float2half_rn(f4[2].x), __float2half_rn(f4[2].y)),
            packh(__float2half_rn(f4[2].z), __float2half_rn(f4[2].w)),
            packh(__float2half_rn(f4[3].x), __float2half_rn(f4[3].y)),
            packh(__float2half_rn(f4[3].z), __float2half_rn(f4[3].w)));
        uint32_t base = (uint32_t)(xm * 256 + xc * 2);
        *(uint4*)(gb + SWB(base))      = h0;
        *(uint4*)(gb + SWB(base + 16)) = h1;
        if (gtid < TILE_M) sIdx0[gtid] = index[v0 + gtid];
        // prefetch second tile
        const int t1 = t0 + stride;
        if (t1 < NTILES) {
            const size_t v1 = (size_t)t1 * TILE_M;
            const float4* xr1 = (const float4*)(x + (v1 + xm) * NCAND + xc);
#pragma unroll
            for (int q = 0; q < 4; ++q) f4[q] = xr1[q];
            if (gtid < TILE_M) idxn = index[v1 + gtid];
        }
    }
    GBAR(gbar);

    for (int t = blockIdx.x * 2 + gid; t < NTILES; t += stride) {
        // ---- L1: relu(x @ W1 + b1) -> P1 ----
        bini(acc, sB1, wn, lane);
        gemm1<2, true>(P0, W1, acc, wm, wn, lane);
        epi<true>(acc, wb, P1off, wm, wn, lane);
        GBAR(gbar);

        // ---- L2: relu(h1 @ W2 + b2) -> P0 ----
        bini(acc, sB2, wn, lane);
        gemm1<8, false>(P1, W2, acc, wm, wn, lane);
        epi<true>(acc, wb, P0off, wm, wn, lane);
        GBAR(gbar);

        // ---- L3: h2 @ W3 + b3 -> P1 (fp16) ----
        bini(acc, sB3, wn, lane);
        gemm1<8, false>(P0, W3, acc, wm, wn, lane);
        epi<false>(acc, wb, P1off, wm, wn, lane);
        GBAR(gbar);

        // ---- stage NEXT tile's x -> P0 (free: last read was L3) ----
        const int tn = t + stride;
        int* sIdxC = pp ? sIdx1 : sIdx0;
        int* sIdxN = pp ? sIdx0 : sIdx1;
        if (tn < NTILES) {
            uint4 h0 = make_uint4(
                packh(__float2half_rn(f4[0].x), __float2half_rn(f4[0].y)),
                packh(__float2half_rn(f4[0].z), __float2half_rn(f4[0].w)),
                packh(__float2half_rn(f4[1].x), __float2half_rn(f4[1].y)),
                packh(__float2half_rn(f4[1].z), __float2half_rn(f4[1].w)));
            uint4 h1 = make_uint4(
                packh(__float2half_rn(f4[2].x), __float2half_rn(f4[2].y)),
                packh(__float2half_rn(f4[2].z), __float2half_rn(f4[2].w)),
                packh(__float2half_rn(f4[3].x), __float2half_rn(f4[3].y)),
                packh(__float2half_rn(f4[3].z), __float2half_rn(f4[3].w)));
            uint32_t base = (uint32_t)(xm * 256 + xc * 2);
            *(uint4*)(gb + SWB(base))      = h0;
            *(uint4*)(gb + SWB(base + 16)) = h1;
            if (gtid < TILE_M) sIdxN[gtid] = idxn;
        }

        // ---- sorted-segment reduce from P1 (half2) -> fp32 global atomics ----
        // 256 threads: 32 col-quads x 8 row-chunks of 16.
        // Sorted index => chunk is single-segment iff first==last (94% of chunks).
        {
            const int quad  = gtid & 31;           // cols 4*quad .. 4*quad+3
            const int rbase = (gtid >> 5) * 16;
            const uint32_t cb = (uint32_t)(quad * 8);
            const int s0 = sIdxC[rbase];
            const int s1 = sIdxC[rbase + 15];
            float a0 = 0.f, a1 = 0.f, a2 = 0.f, a3 = 0.f;
            if (s0 == s1) {
                // fast path: branch-free sum of 16 rows
#pragma unroll
                for (int r = 0; r < 16; ++r) {
                    uint32_t off = SWB((uint32_t)((rbase + r) * 256) + cb);
                    uint2 u = *(const uint2*)(gb + 32768 + off);
                    float2 g0 = __half22float2(u2h2(u.x));
                    float2 g1 = __half22float2(u2h2(u.y));
                    a0 += g0.x; a1 += g0.y; a2 += g1.x; a3 += g1.y;
                }
                float* dst = &g_agg[s0 * EMB + quad * 4];
                atomicAdd(dst + 0, a0); atomicAdd(dst + 1, a1);
                atomicAdd(dst + 2, a2); atomicAdd(dst + 3, a3);
            } else {
                // slow path: per-row flush on boundary
                int cur = s0;
#pragma unroll 4
                for (int r = 0; r < 16; ++r) {
                    int ix = sIdxC[rbase + r];
                    if (ix != cur) {
                        float* dst = &g_agg[cur * EMB + quad * 4];
                        atomicAdd(dst + 0, a0); atomicAdd(dst + 1, a1);
                        atomicAdd(dst + 2, a2); atomicAdd(dst + 3, a3);
                        a0 = a1 = a2 = a3 = 0.f; cur = ix;
                    }
                    uint32_t off = SWB((uint32_t)((rbase + r) * 256) + cb);
                    uint2 u = *(const uint2*)(gb + 32768 + off);
                    float2 g0 = __half22float2(u2h2(u.x));
                    float2 g1 = __half22float2(u2h2(u.y));
                    a0 += g0.x; a1 += g0.y; a2 += g1.x; a3 += g1.y;
                }
                float* dst = &g_agg[cur * EMB + quad * 4];
                atomicAdd(dst + 0, a0); atomicAdd(dst + 1, a1);
                atomicAdd(dst + 2, a2); atomicAdd(dst + 3, a3);
            }
        }

        // ---- prefetch tile t+2*stride (consumed at next stage) ----
        const int tn2 = t + 2 * stride;
        if (tn2 < NTILES) {
            const size_t v2 = (size_t)tn2 * TILE_M;
            const float4* xr = (const float4*)(x + (v2 + xm) * NCAND + xc);
#pragma unroll
            for (int q = 0; q < 4; ++q) f4[q] = xr[q];
            if (gtid < TILE_M) idxn = index[v2 + gtid];
        }
        GBAR(gbar);
        pp ^= 1;
    }
}

// ------------------------------------------------------------------
// Global MLP: 512 CTAs x 8 segments — each weight LDG reused 8x
// ------------------------------------------------------------------
__global__ __launch_bounds__(128)
void global_mlp_kernel(const float* __restrict__ gW1, const float* __restrict__ gb1,
                       const float* __restrict__ gW2, const float* __restrict__ gb2,
                       const float* __restrict__ gW3, const float* __restrict__ gb3,
                       float* __restrict__ out) {
    __shared__ float sIn[8][EMB];
    __shared__ float sH[8][EMB];
    __shared__ float sG[8][EMB];
    const int tid = threadIdx.x;
    const int seg0 = blockIdx.x * 8;

#pragma unroll
    for (int j = 0; j < 8; ++j) sIn[j][tid] = g_agg[(seg0 + j) * EMB + tid];
    __syncthreads();

    // layer g1: 8 segments share each weight load
    {
        const float b1 = __ldg(&gb1[tid]);
        float a[8];
#pragma unroll
        for (int j = 0; j < 8; ++j) a[j] = 0.f;
#pragma unroll 4
        for (int k = 0; k < EMB; ++k) {
            const float w = __ldg(&gW1[k * EMB + tid]);
#pragma unroll
            for (int j = 0; j < 8; ++j) a[j] += sIn[j][k] * w;
        }
#pragma unroll
        for (int j = 0; j < 8; ++j) sH[j][tid] = fmaxf(a[j] + b1, 0.0f);
    }
    __syncthreads();

    // layer g2
    {
        const float b2 = __ldg(&gb2[tid]);
        float a[8];
#pragma unroll
        for (int j = 0; j < 8; ++j) a[j] = 0.f;
#pragma unroll 4
        for (int k = 0; k < EMB; ++k) {
            const float w = __ldg(&gW2[k * EMB + tid]);
#pragma unroll
            for (int j = 0; j < 8; ++j) a[j] += sH[j][k] * w;
        }
#pragma unroll
        for (int j = 0; j < 8; ++j) sG[j][tid] = fmaxf(a[j] + b2, 0.0f);
    }
    __syncthreads();

    // layer g3 + log_softmax: warp w handles segments seg0+w and seg0+w+4
    {
        const int c = tid & 31;
        const float b3 = __ldg(&gb3[c]);
#pragma unroll
        for (int rot = 0; rot < 2; ++rot) {
            const int j = (tid >> 5) + rot * 4;
            float s0 = 0.f, s1 = 0.f, s2 = 0.f, s3 = 0.f;
#pragma unroll 8
            for (int k = 0; k < EMB; k += 4) {
                s0 += sG[j][k]     * __ldg(&gW3[(k)     * NCAND + c]);
                s1 += sG[j][k + 1] * __ldg(&gW3[(k + 1) * NCAND + c]);
                s2 += sG[j][k + 2] * __ldg(&gW3[(k + 2) * NCAND + c]);
                s3 += sG[j][k + 3] * __ldg(&gW3[(k + 3) * NCAND + c]);
            }
            float sc = (s0 + s1) + (s2 + s3) + b3;
            float mx = sc;
#pragma unroll
            for (int o = 16; o > 0; o >>= 1) mx = fmaxf(mx, __shfl_xor_sync(0xffffffffu, mx, o));
            float e = expf(sc - mx);
            float ssum = e;
#pragma unroll
            for (int o = 16; o > 0; o >>= 1) ssum += __shfl_xor_sync(0xffffffffu, ssum, o);
            out[(seg0 + j) * NCAND + c] = sc - mx - logf(ssum);
        }
    }
}

extern "C" void kernel_launch(void* const* d_in, const int* in_sizes, int n_in,
                              void* d_out, int out_size) {
    const float* x     = (const float*)d_in[0];
    const int*   index = (const int*)d_in[1];
    const float* lW1 = (const float*)d_in[2];
    const float* lb1 = (const float*)d_in[3];
    const float* lW2 = (const float*)d_in[4];
    const float* lb2 = (const float*)d_in[5];
    const float* lW3 = (const float*)d_in[6];
    const float* lb3 = (const float*)d_in[7];
    const float* gW1 = (const float*)d_in[8];
    const float* gb1 = (const float*)d_in[9];
    const float* gW2 = (const float*)d_in[10];
    const float* gb2 = (const float*)d_in[11];
    const float* gW3 = (const float*)d_in[12];
    const float* gb3 = (const float*)d_in[13];
    float* out = (float*)d_out;

    cudaFuncSetAttribute(local_mlp_hmma,
                         cudaFuncAttributeMaxDynamicSharedMemorySize, DYN_BYTES);

    prep_weights<<<160, 256>>>(lW1, lW2, lW3);
    local_mlp_hmma<<<148, 512, DYN_BYTES>>>(x, index, lb1, lb2, lb3);
    global_mlp_kernel<<<NSEG / 8, 128>>>(gW1, gb1, gW2, gb2, gW3, gb3, out);
}

// round 17
// speedup vs baseline: 1.1883x; 1.0064x over previous
#include <cuda_runtime.h>
#include <cuda_fp16.h>
#include <cstdint>
#include <cstring>
#include <math.h>

#define NSEG   4096
#define NVOT   1048576
#define NCAND  32
#define EMB    128
#define TILE_M 128
#define NTILES (NVOT / TILE_M)   // 8192

// 256B-pitch shared-tile swizzle: XOR 16B-unit index with row low bits
#define SWB(o) ((o) ^ (((o) >> 4) & 0x70))

// ------------------------------------------------------------------
// Device scratch (allocation-free rule: __device__ globals)
// ------------------------------------------------------------------
__device__ float g_agg[NSEG * EMB];
__device__ __half g_w1[128 * 64];
__device__ __half g_w2[128 * 128];
__device__ __half g_w3[128 * 128];

// ------------------------------------------------------------------
// PTX helpers (sm_80-era: legal in compute_103 PTX)
// ------------------------------------------------------------------
__device__ __forceinline__ uint32_t smem_u32(const void* p) {
    uint32_t a;
    asm("{ .reg .u64 t; cvta.to.shared.u64 t, %1; cvt.u32.u64 %0, t; }" : "=r"(a) : "l"(p));
    return a;
}
__device__ __forceinline__ void ldsm4(uint32_t r[4], uint32_t addr) {
    asm volatile("ldmatrix.sync.aligned.m8n8.x4.shared.b16 {%0,%1,%2,%3}, [%4];"
                 : "=r"(r[0]), "=r"(r[1]), "=r"(r[2]), "=r"(r[3]) : "r"(addr));
}
// fp16-accumulate HMMA
__device__ __forceinline__ void mma16816h(uint32_t c[2], const uint32_t a[4], const uint32_t b[2]) {
    asm volatile("mma.sync.aligned.m16n8k16.row.col.f16.f16.f16.f16 "
                 "{%0,%1}, {%2,%3,%4,%5}, {%6,%7}, {%0,%1};"
                 : "+r"(c[0]), "+r"(c[1])
                 : "r"(a[0]), "r"(a[1]), "r"(a[2]), "r"(a[3]), "r"(b[0]), "r"(b[1]));
}
__device__ __forceinline__ uint32_t packh(__half a, __half b) {
    __half2 t = __halves2half2(a, b);
    uint32_t r; memcpy(&r, &t, 4); return r;
}
__device__ __forceinline__ __half2 u2h2(uint32_t u) {
    __half2 h; memcpy(&h, &u, 4); return h;
}
__device__ __forceinline__ uint32_t h22u(__half2 h) {
    uint32_t u; memcpy(&u, &h, 4); return u;
}
#define GBAR(id) asm volatile("bar.sync %0, %1;" :: "r"(id), "r"(256) : "memory")

// ------------------------------------------------------------------
// Weight prep + agg zero in ONE wide launch:
// blocks < 160 transpose/convert weights; ALL 2048 blocks zero a 1KB slice
// ------------------------------------------------------------------
__global__ void prep_weights(const float* __restrict__ lW1,
                             const float* __restrict__ lW2,
                             const float* __restrict__ lW3) {
    const int tid = threadIdx.x;
    if (blockIdx.x < 160) {
        int i = blockIdx.x * 256 + tid;
        if (i < 8192)       { int n = i >> 6, k = i & 63;
                              g_w1[i] = __float2half_rn((k < 32) ? lW1[k * 128 + n] : 0.0f); }
        else if (i < 24576) { int e = i - 8192;  int n = e >> 7, k = e & 127;
                              g_w2[e] = __float2half_rn(lW2[k * 128 + n]); }
        else if (i < 40960) { int e = i - 24576; int n = e >> 7, k = e & 127;
                              g_w3[e] = __float2half_rn(lW3[k * 128 + n]); }
    }
    // zero g_agg: 2048 blocks x 256 floats
    g_agg[blockIdx.x * 256 + tid] = 0.0f;
}

// ------------------------------------------------------------------
// Local MLP: persistent HMMA kernel (fp16 acc), two 256-thread groups
// smem layout (byte offsets from 1024-aligned base)
// ------------------------------------------------------------------
#define OFF_W1  0          /* [128][pitch 80B], k<32 used : 10240 */
#define OFF_W2  10240      /* [128][256B] swizzled : 32768 */
#define OFF_W3  43008
#define OFF_GRP 75776      /* per-group: P0 (32768) + P1 (32768) */
#define OFF_B1  206848     /* half2[64] per layer */
#define OFF_B2  207360
#define OFF_B3  207872
#define OFF_IDX 208384     /* per group: 2 x 128 ints (ping-pong), 1024B each */
#define DYN_BYTES (210432 + 1024)

// Single-pass fp16-acc GEMM per group: D += A * W.  M=128 x N=128 x K=16*KSTEPS.
// 8 warps/group: wm = (gwid>>2)*64 (4 m16 frags), wn = (gwid&3)*32.
template<int KSTEPS, bool ISW1>
__device__ __forceinline__ void gemm1(uint32_t aB, uint32_t wB,
                                      uint32_t acc[4][4][2], int wm, int wn, int lane) {
    const int r  = lane & 7;
    const int hs = (lane >> 3) & 1;
    const int qs = (lane >> 4) & 1;
    int am[4];
#pragma unroll
    for (int f = 0; f < 4; ++f) am[f] = (wm + f * 16 + r + hs * 8) * 256;
    const int bn0 = wn + r + qs * 8;
    const int bn1 = bn0 + 16;

#pragma unroll
    for (int ks = 0; ks < KSTEPS; ++ks) {
        const int ka = (ks * 16 + qs * 8) * 2;
        const int kb = (ks * 16 + hs * 8) * 2;
        uint32_t a[4][4], bq0[4], bq1[4];
        if (ISW1) {
            ldsm4(bq0, wB + bn0 * 80 + kb);
            ldsm4(bq1, wB + bn1 * 80 + kb);
        } else {
            ldsm4(bq0, wB + SWB(bn0 * 256 + kb));
            ldsm4(bq1, wB + SWB(bn1 * 256 + kb));
        }
#pragma unroll
        for (int f = 0; f < 4; ++f) ldsm4(a[f], aB + SWB(am[f] + ka));
#pragma unroll
        for (int f = 0; f < 4; ++f) {
            mma16816h(acc[f][0], a[f], bq0 + 0);
            mma16816h(acc[f][1], a[f], bq0 + 2);
            mma16816h(acc[f][2], a[f], bq1 + 0);
            mma16816h(acc[f][3], a[f], bq1 + 2);
        }
    }
}

// initialize accumulators with the layer bias (HMMA folds C=bias for free)
__device__ __forceinline__ void bini(uint32_t acc[4][4][2], const uint32_t* bias2,
                                     int wn, int lane) {
    const int nc0 = wn + 2 * (lane & 3);
#pragma unroll
    for (int nt = 0; nt < 4; ++nt) {
        const uint32_t b = bias2[(nc0 + nt * 8) >> 1];
#pragma unroll
        for (int f = 0; f < 4; ++f) { acc[f][nt][0] = b; acc[f][nt][1] = b; }
    }
}

// optional relu -> fp16 buffer (swizzled, 256B pitch); bias already in acc
template<bool RELU>
__device__ __forceinline__ void epi(uint32_t acc[4][4][2], char* wb, uint32_t offD,
                                    int wm, int wn, int lane) {
    const int mr  = wm + (lane >> 2);
    const int nc0 = wn + 2 * (lane & 3);
    const __half2 z2 = __float2half2_rn(0.0f);
#pragma unroll
    for (int f = 0; f < 4; ++f)
#pragma unroll
        for (int nt = 0; nt < 4; ++nt) {
            const int n = nc0 + nt * 8;
#pragma unroll
            for (int h = 0; h < 2; ++h) {
                const int m = mr + f * 16 + h * 8;
                __half2 v = u2h2(acc[f][nt][h]);
                if (RELU) v = __hmax2(v, z2);
                *(uint32_t*)(wb + offD + SWB((uint32_t)(m * 256 + n * 2))) = h22u(v);
            }
        }
}

__global__ __launch_bounds__(512, 1)
void local_mlp_hmma(const float* __restrict__ x, const int* __restrict__ index,
                    const float* __restrict__ lb1, const float* __restrict__ lb2,
                    const float* __restrict__ lb3) {
    extern __shared__ char dsm[];
    char* wb = (char*)(((uintptr_t)dsm + 1023) & ~(uintptr_t)1023);
    const uint32_t wb32 = smem_u32(wb);

    const int tid  = threadIdx.x;
    const int gid  = tid >> 8;          // worker group 0/1
    const int gtid = tid & 255;
    const int gwid = gtid >> 5;         // warp within group (0..7)
    const int lane = tid & 31;
    const int wm   = (gwid >> 2) * 64;
    const int wn   = (gwid & 3) * 32;
    const int gbar = 1 + gid;           // named barrier id

    // ---- stage weights once per CTA (all 512 threads) ----
    for (int e = tid; e < 2048; e += 512) {     // W2/W3: 16B chunks
        int n = e >> 4, k0 = (e & 15) * 8;
        uint32_t off = (uint32_t)SWB(n * 256 + k0 * 2);
        *(uint4*)(wb + OFF_W2 + off) = *(const uint4*)(g_w2 + n * 128 + k0);
        *(uint4*)(wb + OFF_W3 + off) = *(const uint4*)(g_w3 + n * 128 + k0);
    }
    for (int e = tid; e < 1024; e += 512) {     // W1: pitch 80B, 8B chunks
        int n = e >> 3, k0 = (e & 7) * 4;
        *(uint2*)(wb + OFF_W1 + (uint32_t)(n * 80 + k0 * 2)) =
            *(const uint2*)(g_w1 + n * 64 + k0);
    }
    uint32_t* sB1 = (uint32_t*)(wb + OFF_B1);
    uint32_t* sB2 = (uint32_t*)(wb + OFF_B2);
    uint32_t* sB3 = (uint32_t*)(wb + OFF_B3);
    if (tid < 64) {
        sB1[tid] = packh(__float2half_rn(lb1[2 * tid]), __float2half_rn(lb1[2 * tid + 1]));
        sB2[tid] = packh(__float2half_rn(lb2[2 * tid]), __float2half_rn(lb2[2 * tid + 1]));
        sB3[tid] = packh(__float2half_rn(lb3[2 * tid]), __float2half_rn(lb3[2 * tid + 1]));
    }
    __syncthreads();

    // per-group buffers
    char* gb = wb + OFF_GRP + gid * 65536;
    const uint32_t P0off = (uint32_t)(OFF_GRP + gid * 65536);
    const uint32_t P1off = P0off + 32768;
    const uint32_t P0 = wb32 + P0off, P1 = wb32 + P1off;
    int* sIdx0 = (int*)(wb + OFF_IDX + gid * 1024);
    int* sIdx1 = sIdx0 + 128;
    const uint32_t W1 = wb32 + OFF_W1, W2 = wb32 + OFF_W2, W3 = wb32 + OFF_W3;

    // x staging coords: each thread handles half a row (16 floats)
    const int xm = gtid >> 1;
    const int xc = (gtid & 1) * 16;
    const int stride = 2 * gridDim.x;

    uint32_t acc[4][4][2];
    float4 f4[4];
    int idxn = 0;
    int pp = 0;

    // ---- prologue: load + stage first tile; prefetch second ----
    {
        const int t0 = blockIdx.x * 2 + gid;
        const size_t v0 = (size_t)t0 * TILE_M;
        const float4* xr = (const float4*)(x + (v0 + xm) * NCAND + xc);
#pragma unroll
        for (int q = 0; q < 4; ++q) f4[q] = xr[q];
        uint4 h0 = make_uint4(
            packh(__float2half_rn(f4[0].x), __float2half_rn(f4[0].y)),
            packh(__float2half_rn(f4[0].z), __float2half_rn(f4[0].w)),
            packh(__float2half_rn(f4[1].x), __float2half_rn(f4[1].y)),
            packh(__float2half_rn(f4[1].z), __float2half_rn(f4[1].w)));
        uint4 h1 = make_uint4(
            packh(__float2half_rn(f4[2].x), __float2half_rn(f4[2].y)),
            packh(__float2half_rn(f4[2].z), __float2half_rn(f4[2].w)),
            packh(__float2half_rn(f4[3].x), __float2half_rn(f4[3].y)),
            packh(__float2half_rn(f4[3].z), __float2half_rn(f4[3].w)));
        uint32_t base = (uint32_t)(xm * 256 + xc * 2);
        *(uint4*)(gb + SWB(base))      = h0;
        *(uint4*)(gb + SWB(base + 16)) = h1;
        if (gtid < TILE_M) sIdx0[gtid] = index[v0 + gtid];
        // prefetch second tile
        const int t1 = t0 + stride;
        if (t1 < NTILES) {
            const size_t v1 = (size_t)t1 * TILE_M;
            const float4* xr1 = (const float4*)(x + (v1 + xm) * NCAND + xc);
#pragma unroll
            for (int q = 0; q < 4; ++q) f4[q] = xr1[q];
            if (gtid < TILE_M) idxn = index[v1 + gtid];
        }
    }
    GBAR(gbar);

    for (int t = blockIdx.x * 2 + gid; t < NTILES; t += stride) {
        // ---- L1: relu(x @ W1 + b1) -> P1 ----
        bini(acc, sB1, wn, lane);
        gemm1<2, true>(P0, W1, acc, wm, wn, lane);
        epi<true>(acc, wb, P1off, wm, wn, lane);
        GBAR(gbar);

        // ---- L2: relu(h1 @ W2 + b2) -> P0 ----
        bini(acc, sB2, wn, lane);
        gemm1<8, false>(P1, W2, acc, wm, wn, lane);
        epi<true>(acc, wb, P0off, wm, wn, lane);
        GBAR(gbar);

        // ---- L3: h2 @ W3 + b3 -> P1 (fp16) ----
        bini(acc, sB3, wn, lane);
        gemm1<8, false>(P0, W3, acc, wm, wn, lane);
        epi<false>(acc, wb, P1off, wm, wn, lane);
        GBAR(gbar);

        // ---- stage NEXT tile's x -> P0 (free: last read was L3) ----
        const int tn = t + stride;
        int* sIdxC = pp ? sIdx1 : sIdx0;
        int* sIdxN = pp ? sIdx0 : sIdx1;
        if (tn < NTILES) {
            uint4 h0 = make_uint4(
                packh(__float2half_rn(f4[0].x), __float2half_rn(f4[0].y)),
                packh(__float2half_rn(f4[0].z), __float2half_rn(f4[0].w)),
                packh(__float2half_rn(f4[1].x), __float2half_rn(f4[1].y)),
                packh(__float2half_rn(f4[1].z), __float2half_rn(f4[1].w)));
            uint4 h1 = make_uint4(
                packh(__float2half_rn(f4[2].x), __float2half_rn(f4[2].y)),
                packh(__float2half_rn(f4[2].z), __float2half_rn(f4[2].w)),
                packh(__float2half_rn(f4[3].x), __float2half_rn(f4[3].y)),
                packh(__float2half_rn(f4[3].z), __float2half_rn(f4[3].w)));
            uint32_t base = (uint32_t)(xm * 256 + xc * 2);
            *(uint4*)(gb + SWB(base))      = h0;
            *(uint4*)(gb + SWB(base + 16)) = h1;
            if (gtid < TILE_M) sIdxN[gtid] = idxn;
        }

        // ---- sorted-segment reduce from P1 (half2) -> fp32 global atomics ----
        // 256 threads: 32 col-quads x 8 row-chunks of 16.
        // Sorted index => chunk is single-segment iff first==last (94% of chunks).
        {
            const int quad  = gtid & 31;           // cols 4*quad .. 4*quad+3
            const int rbase = (gtid >> 5) * 16;
            const uint32_t cb = (uint32_t)(quad * 8);
            const int s0 = sIdxC[rbase];
            const int s1 = sIdxC[rbase + 15];
            float a0 = 0.f, a1 = 0.f, a2 = 0.f, a3 = 0.f;
            if (s0 == s1) {
                // fast path: branch-free sum of 16 rows
#pragma unroll
                for (int r = 0; r < 16; ++r) {
                    uint32_t off = SWB((uint32_t)((rbase + r) * 256) + cb);
                    uint2 u = *(const uint2*)(gb + 32768 + off);
                    float2 g0 = __half22float2(u2h2(u.x));
                    float2 g1 = __half22float2(u2h2(u.y));
                    a0 += g0.x; a1 += g0.y; a2 += g1.x; a3 += g1.y;
                }
                float* dst = &g_agg[s0 * EMB + quad * 4];
                atomicAdd(dst + 0, a0); atomicAdd(dst + 1, a1);
                atomicAdd(dst + 2, a2); atomicAdd(dst + 3, a3);
            } else {
                // slow path: per-row flush on boundary
                int cur = s0;
#pragma unroll 4
                for (int r = 0; r < 16; ++r) {
                    int ix = sIdxC[rbase + r];
                    if (ix != cur) {
                        float* dst = &g_agg[cur * EMB + quad * 4];
                        atomicAdd(dst + 0, a0); atomicAdd(dst + 1, a1);
                        atomicAdd(dst + 2, a2); atomicAdd(dst + 3, a3);
                        a0 = a1 = a2 = a3 = 0.f; cur = ix;
                    }
                    uint32_t off = SWB((uint32_t)((rbase + r) * 256) + cb);
                    uint2 u = *(const uint2*)(gb + 32768 + off);
                    float2 g0 = __half22float2(u2h2(u.x));
                    float2 g1 = __half22float2(u2h2(u.y));
                    a0 += g0.x; a1 += g0.y; a2 += g1.x; a3 += g1.y;
                }
                float* dst = &g_agg[cur * EMB + quad * 4];
                atomicAdd(dst + 0, a0); atomicAdd(dst + 1, a1);
                atomicAdd(dst + 2, a2); atomicAdd(dst + 3, a3);
            }
        }

        // ---- prefetch tile t+2*stride (consumed at next stage) ----
        const int tn2 = t + 2 * stride;
        if (tn2 < NTILES) {
            const size_t v2 = (size_t)tn2 * TILE_M;
            const float4* xr = (const float4*)(x + (v2 + xm) * NCAND + xc);
#pragma unroll
            for (int q = 0; q < 4; ++q) f4[q] = xr[q];
            if (gtid < TILE_M) idxn = index[v2 + gtid];
        }
        GBAR(gbar);
        pp ^= 1;
    }
}

// ------------------------------------------------------------------
// Global MLP: 512 CTAs x 8 segments — each weight LDG reused 8x
// ------------------------------------------------------------------
__global__ __launch_bounds__(128)
void global_mlp_kernel(const float* __restrict__ gW1, const float* __restrict__ gb1,
                       const float* __restrict__ gW2, const float* __restrict__ gb2,
                       const float* __restrict__ gW3, const float* __restrict__ gb3,
                       float* __restrict__ out) {
    __shared__ float sIn[8][EMB];
    __shared__ float sH[8][EMB];
    __shared__ float sG[8][EMB];
    const int tid = threadIdx.x;
    const int seg0 = blockIdx.x * 8;

#pragma unroll
    for (int j = 0; j < 8; ++j) sIn[j][tid] = g_agg[(seg0 + j) * EMB + tid];
    __syncthreads();

    // layer g1: 8 segments share each weight load
    {
        const float b1 = __ldg(&gb1[tid]);
        float a[8];
#pragma unroll
        for (int j = 0; j < 8; ++j) a[j] = 0.f;
#pragma unroll 4
        for (int k = 0; k < EMB; ++k) {
            const float w = __ldg(&gW1[k * EMB + tid]);
#pragma unroll
            for (int j = 0; j < 8; ++j) a[j] += sIn[j][k] * w;
        }
#pragma unroll
        for (int j = 0; j < 8; ++j) sH[j][tid] = fmaxf(a[j] + b1, 0.0f);
    }
    __syncthreads();

    // layer g2
    {
        const float b2 = __ldg(&gb2[tid]);
        float a[8];
#pragma unroll
        for (int j = 0; j < 8; ++j) a[j] = 0.f;
#pragma unroll 4
        for (int k = 0; k < EMB; ++k) {
            const float w = __ldg(&gW2[k * EMB + tid]);
#pragma unroll
            for (int j = 0; j < 8; ++j) a[j] += sH[j][k] * w;
        }
#pragma unroll
        for (int j = 0; j < 8; ++j) sG[j][tid] = fmaxf(a[j] + b2, 0.0f);
    }
    __syncthreads();

    // layer g3 + log_softmax: warp w handles segments seg0+w and seg0+w+4
    {
        const int c = tid & 31;
        const float b3 = __ldg(&gb3[c]);
#pragma unroll
        for (int rot = 0; rot < 2; ++rot) {
            const int j = (tid >> 5) + rot * 4;
            float s0 = 0.f, s1 = 0.f, s2 = 0.f, s3 = 0.f;
#pragma unroll 8
            for (int k = 0; k < EMB; k += 4) {
                s0 += sG[j][k]     * __ldg(&gW3[(k)     * NCAND + c]);
                s1 += sG[j][k + 1] * __ldg(&gW3[(k + 1) * NCAND + c]);
                s2 += sG[j][k + 2] * __ldg(&gW3[(k + 2) * NCAND + c]);
                s3 += sG[j][k + 3] * __ldg(&gW3[(k + 3) * NCAND + c]);
            }
            float sc = (s0 + s1) + (s2 + s3) + b3;
            float mx = sc;
#pragma unroll
            for (int o = 16; o > 0; o >>= 1) mx = fmaxf(mx, __shfl_xor_sync(0xffffffffu, mx, o));
            float e = expf(sc - mx);
            float ssum = e;
#pragma unroll
            for (int o = 16; o > 0; o >>= 1) ssum += __shfl_xor_sync(0xffffffffu, ssum, o);
            out[(seg0 + j) * NCAND + c] = sc - mx - logf(ssum);
        }
    }
}

extern "C" void kernel_launch(void* const* d_in, const int* in_sizes, int n_in,
                              void* d_out, int out_size) {
    const float* x     = (const float*)d_in[0];
    const int*   index = (const int*)d_in[1];
    const float* lW1 = (const float*)d_in[2];
    const float* lb1 = (const float*)d_in[3];
    const float* lW2 = (const float*)d_in[4];
    const float* lb2 = (const float*)d_in[5];
    const float* lW3 = (const float*)d_in[6];
    const float* lb3 = (const float*)d_in[7];
    const float* gW1 = (const float*)d_in[8];
    const float* gb1 = (const float*)d_in[9];
    const float* gW2 = (const float*)d_in[10];
    const float* gb2 = (const float*)d_in[11];
    const float* gW3 = (const float*)d_in[12];
    const float* gb3 = (const float*)d_in[13];
    float* out = (float*)d_out;

    cudaFuncSetAttribute(local_mlp_hmma,
                         cudaFuncAttributeMaxDynamicSharedMemorySize, DYN_BYTES);

    prep_weights<<<2048, 256>>>(lW1, lW2, lW3);
    local_mlp_hmma<<<148, 512, DYN_BYTES>>>(x, index, lb1, lb2, lb3);
    global_mlp_kernel<<<NSEG / 8, 128>>>(gW1, gb1, gW2, gb2, gW3, gb3, out);
}